// round 13
// baseline (speedup 1.0000x reference)
#include <cuda_runtime.h>
#include <math.h>

#define LATENT 256
#define HID 512
#define NT 16
#define MAXB 2048

typedef unsigned long long u64;

// scratch (allocation-free rule: device globals)
__device__ float g_h[MAXB * HID];
__device__ float g_we1s[HID * HID];
__device__ float g_p[MAXB];
__device__ float g_part[4][MAXB * HID];   // split-K partial sums

// ---- f32x2 helpers: pairs flow straight from LDS, no packing in loop ----
__device__ __forceinline__ void fma2(u64& d, u64 a, u64 b) {
    asm("fma.rn.f32x2 %0, %1, %2, %3;" : "=l"(d) : "l"(a), "l"(b), "l"(d));
}
__device__ __forceinline__ float2 upk2(u64 v) {
    float2 f; asm("mov.b64 {%0, %1}, %2;" : "=f"(f.x), "=f"(f.y) : "l"(v)); return f;
}

// ---------------------------------------------------------------------------
// W_e1_sum = W_e1[0:H, :] + W_e1[H:2H, :]
// ---------------------------------------------------------------------------
__global__ __launch_bounds__(256)
void wsum_kernel(const float* __restrict__ W, float* __restrict__ o)
{
    int i = blockIdx.x * 256 + threadIdx.x;
    float4 a = reinterpret_cast<const float4*>(W)[i];
    float4 b = reinterpret_cast<const float4*>(W + (size_t)HID * HID)[i];
    a.x += b.x; a.y += b.y; a.z += b.z; a.w += b.w;
    reinterpret_cast<float4*>(o)[i] = a;
}

// ---------------------------------------------------------------------------
// Split-K SGEMM partial, K-PAIRED FFMA2 inner loop.
//   Cpart[z] = A[:, kOff:kOff+kLen] @ B[kOff:kOff+kLen, :]   (raw, no bias)
// BM=64 BN=64 BK=16, 128 threads, 8x4 microtile. Smem holds k-PAIR
// interleaved operands: As2[kp][row][2] = (a[2kp],a[2kp+1]),
// Bs2[kp][col][2] = (b[2kp],b[2kp+1]). acc2 packs partial sums over
// (even k, odd k); epilogue adds lo+hi. Zero MOV packing in the loop.
// grid = (N/64, ceil(M/64), nsplit); kOff = blockIdx.z * kLen.
// ---------------------------------------------------------------------------
__global__ __launch_bounds__(128)
void gemm_part(const float* __restrict__ A, int lda,
               const float* __restrict__ B,
               float* __restrict__ Cpart,
               int M, int N, int kLen)
{
    constexpr int BM = 64, BN = 64, BK = 16;
    constexpr int KP = BK / 2;          // 8 k-pairs per tile
    constexpr int AW = BM * 2 + 4;      // padded row length (floats)
    constexpr int BW = BN * 2 + 4;
    __shared__ __align__(16) float As2[2][KP][AW];
    __shared__ __align__(16) float Bs2[2][KP][BW];

    const int tx = threadIdx.x;
    const int rowBase = blockIdx.y * BM;
    const int colBase = blockIdx.x * BN;
    const int kOff = blockIdx.z * kLen;
    float* C = Cpart + (size_t)blockIdx.z * MAXB * HID;

    // A loader: rows ar, ar+32; k's ac..ac+3 (one float4 each)
    const int ar = tx >> 2;             // 0..31
    const int ac = (tx & 3) << 2;       // 0,4,8,12
    // B loader: k rows 2*brp, 2*brp+1; cols bc..bc+3
    const int brp = tx >> 4;            // 0..7
    const int bc = (tx & 15) << 2;      // 0..60

    // compute mapping
    const int rm0 = (tx >> 4) << 3;     // 0..56
    const int cn0 = (tx & 15) << 2;     // 0..60

    const bool mok0 = (rowBase + ar) < M;
    const bool mok1 = (rowBase + ar + 32) < M;
    const float* Ap0 = A + (size_t)(rowBase + ar) * lda + kOff + ac;
    const float* Ap1 = Ap0 + (size_t)32 * lda;
    const float* Bp0 = B + (size_t)(kOff + 2 * brp) * N + colBase + bc;
    const float* Bp1 = Bp0 + N;

    u64 acc2[8][4];
    #pragma unroll
    for (int i = 0; i < 8; i++)
        #pragma unroll
        for (int j = 0; j < 4; j++)
            acc2[i][j] = 0ull;

    // ---- stage 0 load ----
    float4 av0 = make_float4(0.f,0.f,0.f,0.f), av1 = av0;
    if (mok0) av0 = *reinterpret_cast<const float4*>(Ap0);
    if (mok1) av1 = *reinterpret_cast<const float4*>(Ap1);
    float4 bv0 = *reinterpret_cast<const float4*>(Bp0);
    float4 bv1 = *reinterpret_cast<const float4*>(Bp1);
    {
        const int kp0 = ac >> 1;        // k-pairs kp0, kp0+1
        *reinterpret_cast<float2*>(&As2[0][kp0    ][ar * 2])        = make_float2(av0.x, av0.y);
        *reinterpret_cast<float2*>(&As2[0][kp0 + 1][ar * 2])        = make_float2(av0.z, av0.w);
        *reinterpret_cast<float2*>(&As2[0][kp0    ][(ar + 32) * 2]) = make_float2(av1.x, av1.y);
        *reinterpret_cast<float2*>(&As2[0][kp0 + 1][(ar + 32) * 2]) = make_float2(av1.z, av1.w);
        *reinterpret_cast<float2*>(&Bs2[0][brp][(bc + 0) * 2]) = make_float2(bv0.x, bv1.x);
        *reinterpret_cast<float2*>(&Bs2[0][brp][(bc + 1) * 2]) = make_float2(bv0.y, bv1.y);
        *reinterpret_cast<float2*>(&Bs2[0][brp][(bc + 2) * 2]) = make_float2(bv0.z, bv1.z);
        *reinterpret_cast<float2*>(&Bs2[0][brp][(bc + 3) * 2]) = make_float2(bv0.w, bv1.w);
    }
    __syncthreads();

    const int nk = kLen / BK;
    for (int t = 0; t < nk; t++) {
        const int buf = t & 1;

        // prefetch next tile
        if (t + 1 < nk) {
            av0 = make_float4(0.f,0.f,0.f,0.f); av1 = av0;
            if (mok0) av0 = *reinterpret_cast<const float4*>(Ap0 + (t + 1) * BK);
            if (mok1) av1 = *reinterpret_cast<const float4*>(Ap1 + (t + 1) * BK);
            bv0 = *reinterpret_cast<const float4*>(Bp0 + (size_t)((t + 1) * BK) * N);
            bv1 = *reinterpret_cast<const float4*>(Bp1 + (size_t)((t + 1) * BK) * N);
        }

        #pragma unroll
        for (int kp = 0; kp < KP; kp++) {
            const float* Ak = &As2[buf][kp][rm0 * 2];
            const float* Bk = &Bs2[buf][kp][cn0 * 2];
            u64 a2[8], b2[4];
            ulonglong2 q;
            q = *reinterpret_cast<const ulonglong2*>(Ak + 0);  a2[0] = q.x; a2[1] = q.y;
            q = *reinterpret_cast<const ulonglong2*>(Ak + 4);  a2[2] = q.x; a2[3] = q.y;
            q = *reinterpret_cast<const ulonglong2*>(Ak + 8);  a2[4] = q.x; a2[5] = q.y;
            q = *reinterpret_cast<const ulonglong2*>(Ak + 12); a2[6] = q.x; a2[7] = q.y;
            q = *reinterpret_cast<const ulonglong2*>(Bk + 0);  b2[0] = q.x; b2[1] = q.y;
            q = *reinterpret_cast<const ulonglong2*>(Bk + 4);  b2[2] = q.x; b2[3] = q.y;
            #pragma unroll
            for (int i = 0; i < 8; i++)
                #pragma unroll
                for (int j = 0; j < 4; j++)
                    fma2(acc2[i][j], a2[i], b2[j]);
        }

        // store prefetched tile
        if (t + 1 < nk) {
            const int nb = buf ^ 1;
            const int kp0 = ac >> 1;
            *reinterpret_cast<float2*>(&As2[nb][kp0    ][ar * 2])        = make_float2(av0.x, av0.y);
            *reinterpret_cast<float2*>(&As2[nb][kp0 + 1][ar * 2])        = make_float2(av0.z, av0.w);
            *reinterpret_cast<float2*>(&As2[nb][kp0    ][(ar + 32) * 2]) = make_float2(av1.x, av1.y);
            *reinterpret_cast<float2*>(&As2[nb][kp0 + 1][(ar + 32) * 2]) = make_float2(av1.z, av1.w);
            *reinterpret_cast<float2*>(&Bs2[nb][brp][(bc + 0) * 2]) = make_float2(bv0.x, bv1.x);
            *reinterpret_cast<float2*>(&Bs2[nb][brp][(bc + 1) * 2]) = make_float2(bv0.y, bv1.y);
            *reinterpret_cast<float2*>(&Bs2[nb][brp][(bc + 2) * 2]) = make_float2(bv0.z, bv1.z);
            *reinterpret_cast<float2*>(&Bs2[nb][brp][(bc + 3) * 2]) = make_float2(bv0.w, bv1.w);
        }
        __syncthreads();
    }

    // epilogue: acc = lo + hi of each k-paired accumulator; raw store
    #pragma unroll
    for (int i = 0; i < 8; i++) {
        int r = rowBase + rm0 + i;
        if (r < M) {
            float4 v;
            float2 f0 = upk2(acc2[i][0]);
            float2 f1 = upk2(acc2[i][1]);
            float2 f2 = upk2(acc2[i][2]);
            float2 f3 = upk2(acc2[i][3]);
            v.x = f0.x + f0.y;
            v.y = f1.x + f1.y;
            v.z = f2.x + f2.y;
            v.w = f3.x + f3.y;
            *reinterpret_cast<float4*>(C + (size_t)r * N + colBase + cn0) = v;
        }
    }
}

// ---------------------------------------------------------------------------
// combine1: h = relu(part0 + part1 + b_z)   (elementwise, float4)
// ---------------------------------------------------------------------------
__global__ __launch_bounds__(256)
void combine1_kernel(const float* __restrict__ p0,
                     const float* __restrict__ p1,
                     const float* __restrict__ bz,
                     float* __restrict__ h)
{
    int i = blockIdx.x * 256 + threadIdx.x;
    float4 a = reinterpret_cast<const float4*>(p0)[i];
    float4 b = reinterpret_cast<const float4*>(p1)[i];
    float4 c = reinterpret_cast<const float4*>(bz)[i & 127];
    float4 v;
    v.x = fmaxf(a.x + b.x + c.x, 0.f);
    v.y = fmaxf(a.y + b.y + c.y, 0.f);
    v.z = fmaxf(a.z + b.z + c.z, 0.f);
    v.w = fmaxf(a.w + b.w + c.w, 0.f);
    reinterpret_cast<float4*>(h)[i] = v;
}

// ---------------------------------------------------------------------------
// combine2: gp[b] = dot(relu(Σ parts[0..3] + b_e1), W_e2) — warp-per-row
// ---------------------------------------------------------------------------
__global__ __launch_bounds__(256)
void combine2_kernel(const float* __restrict__ parts,
                     const float* __restrict__ be1,
                     const float* __restrict__ we2,
                     float* __restrict__ gp, int Bsz)
{
    const int warp = threadIdx.x >> 5, lane = threadIdx.x & 31;
    const int r = blockIdx.x * 8 + warp;
    if (r >= Bsz) return;

    const float4* P0 = reinterpret_cast<const float4*>(parts + (size_t)r * HID);
    const float4* P1 = reinterpret_cast<const float4*>(parts + (size_t)MAXB * HID + (size_t)r * HID);
    const float4* P2 = reinterpret_cast<const float4*>(parts + (size_t)2 * MAXB * HID + (size_t)r * HID);
    const float4* P3 = reinterpret_cast<const float4*>(parts + (size_t)3 * MAXB * HID + (size_t)r * HID);
    const float4* B4 = reinterpret_cast<const float4*>(be1);
    const float4* W4 = reinterpret_cast<const float4*>(we2);

    float s = 0.f;
    #pragma unroll
    for (int q = 0; q < 4; q++) {
        int f = q * 32 + lane;
        float4 a = P0[f], b = P1[f], c = P2[f], d = P3[f];
        float4 bb = B4[f], w = W4[f];
        float x0 = fmaxf(a.x + b.x + c.x + d.x + bb.x, 0.f);
        float x1 = fmaxf(a.y + b.y + c.y + d.y + bb.y, 0.f);
        float x2 = fmaxf(a.z + b.z + c.z + d.z + bb.z, 0.f);
        float x3 = fmaxf(a.w + b.w + c.w + d.w + bb.w, 0.f);
        s = fmaf(x0, w.x, s);
        s = fmaf(x1, w.y, s);
        s = fmaf(x2, w.z, s);
        s = fmaf(x3, w.w, s);
    }
    #pragma unroll
    for (int off = 16; off; off >>= 1)
        s += __shfl_down_sync(0xffffffffu, s, off);
    if (lane == 0) gp[r] = s;
}

// ---------------------------------------------------------------------------
// finalize: grid (Bsz, 2).
//   y==0: logits[t] = h[b].W_node[:,t] + b_node[t]; broadcast over N rows.
//   y==1: p = sigmoid(g_p[b] + b_e2); strict-lower-triangle write.
// ---------------------------------------------------------------------------
__global__ __launch_bounds__(256)
void finalize_kernel(const float* __restrict__ g_h_p,
                     const float* __restrict__ gp,
                     const float* __restrict__ W_node,
                     const float* __restrict__ b_node,
                     const float* __restrict__ b_e2,
                     float* __restrict__ out,
                     int Bsz, int N, int has_edges)
{
    const int b = blockIdx.x;
    const int tid = threadIdx.x;
    const int warp = tid >> 5, lane = tid & 31;

    if (blockIdx.y == 0) {
        __shared__ float sh_h[HID];
        __shared__ float sh_logits[NT];
        __shared__ float sacc[8][4][4];

        {
            const float2* hp = reinterpret_cast<const float2*>(g_h_p + (size_t)b * HID);
            reinterpret_cast<float2*>(sh_h)[tid] = hp[tid];
        }
        __syncthreads();

        const float4* W4 = reinterpret_cast<const float4*>(W_node);
        float a0 = 0.f, a1 = 0.f, a2 = 0.f, a3 = 0.f;
        #pragma unroll
        for (int i = 0; i < (HID * NT / 4) / 256; i++) {
            int j = tid + i * 256;
            float hv = sh_h[j >> 2];
            float4 w = W4[j];
            a0 = fmaf(hv, w.x, a0);
            a1 = fmaf(hv, w.y, a1);
            a2 = fmaf(hv, w.z, a2);
            a3 = fmaf(hv, w.w, a3);
        }
        #pragma unroll
        for (int off = 16; off >= 4; off >>= 1) {
            a0 += __shfl_down_sync(0xffffffffu, a0, off);
            a1 += __shfl_down_sync(0xffffffffu, a1, off);
            a2 += __shfl_down_sync(0xffffffffu, a2, off);
            a3 += __shfl_down_sync(0xffffffffu, a3, off);
        }
        if (lane < 4) {
            sacc[warp][lane][0] = a0;
            sacc[warp][lane][1] = a1;
            sacc[warp][lane][2] = a2;
            sacc[warp][lane][3] = a3;
        }
        __syncthreads();
        if (tid < NT) {
            float s = 0.f;
            #pragma unroll
            for (int w = 0; w < 8; w++)
                s += sacc[w][tid >> 2][tid & 3];
            sh_logits[tid] = s + b_node[tid];
        }
        __syncthreads();

        size_t base1 = (size_t)b * N * NT;
        if (((N * NT) & 3) == 0) {
            float4 myv = *reinterpret_cast<const float4*>(&sh_logits[(tid & 3) << 2]);
            float4* o4 = reinterpret_cast<float4*>(out + base1);
            int n4 = (N * NT) >> 2;
            for (int i = tid; i < n4; i += 256)
                o4[i] = myv;
        } else {
            for (int i = tid; i < N * NT; i += 256)
                out[base1 + i] = sh_logits[i & (NT - 1)];
        }
        return;
    }

    if (!has_edges) return;
    const float p = 1.f / (1.f + expf(-(gp[b] + b_e2[0])));
    size_t base2 = (size_t)Bsz * N * NT + (size_t)b * N * N;

    if (N == 128) {
        const int j0 = lane << 2;
        float4* rowp = reinterpret_cast<float4*>(out + base2)
                       + (size_t)warp * 32 + lane;
        #pragma unroll
        for (int r = 0; r < 16; r++) {
            const int i = warp + (r << 3);
            const int d = i - j0;
            float4 v;
            v.x = (d > 0) ? p : 0.f;
            v.y = (d > 1) ? p : 0.f;
            v.z = (d > 2) ? p : 0.f;
            v.w = (d > 3) ? p : 0.f;
            *rowp = v;
            rowp += 8 * 32;
        }
    } else if ((N & 3) == 0) {
        float4* e4 = reinterpret_cast<float4*>(out + base2);
        const int nr4 = N >> 2;
        for (int i = warp; i < N; i += 8) {
            float4* row = e4 + (size_t)i * nr4;
            for (int c = lane; c < nr4; c += 32) {
                int j0 = c << 2;
                float4 v;
                v.x = (j0 + 0 < i) ? p : 0.f;
                v.y = (j0 + 1 < i) ? p : 0.f;
                v.z = (j0 + 2 < i) ? p : 0.f;
                v.w = (j0 + 3 < i) ? p : 0.f;
                row[c] = v;
            }
        }
    } else {
        for (int i = warp; i < N; i += 8) {
            float* row = out + base2 + (size_t)i * N;
            for (int j = lane; j < N; j += 32)
                row[j] = (j < i) ? p : 0.f;
        }
    }
}

// ---------------------------------------------------------------------------
// Inputs (metadata order): z, num_nodes, W_z, b_z, W_node, b_node,
//                          W_e1, b_e1, W_e2, b_e2
// num_nodes sits in device memory; derive N on host from out_size.
// ---------------------------------------------------------------------------
extern "C" void kernel_launch(void* const* d_in, const int* in_sizes, int n_in,
                              void* d_out, int out_size)
{
    const float* z      = (const float*)d_in[0];
    const float* W_z    = (const float*)d_in[2];
    const float* b_z    = (const float*)d_in[3];
    const float* W_node = (const float*)d_in[4];
    const float* b_node = (const float*)d_in[5];
    const float* W_e1   = (const float*)d_in[6];
    const float* b_e1   = (const float*)d_in[7];
    const float* W_e2   = (const float*)d_in[8];
    const float* b_e2   = (const float*)d_in[9];
    float* out = (float*)d_out;

    int Bsz = in_sizes[0] / LATENT;
    long per = (long)out_size / (long)Bsz;

    double disc = (double)NT * NT + 4.0 * (double)per;
    int N = (int)((-(double)NT + sqrt(disc)) * 0.5 + 0.5);
    int has_edges = 1;
    if ((long)N * N + (long)NT * N != per) {
        N = (int)(per / NT);
        has_edges = 0;
    }

    float *gh = nullptr, *gws = nullptr, *gpp = nullptr, *gpart = nullptr;
    cudaGetSymbolAddress((void**)&gh,    g_h);
    cudaGetSymbolAddress((void**)&gws,   g_we1s);
    cudaGetSymbolAddress((void**)&gpp,   g_p);
    cudaGetSymbolAddress((void**)&gpart, g_part);

    // W_e1 half-sum
    wsum_kernel<<<(HID * HID / 4) / 256, 256>>>(W_e1, gws);

    // gemm1 split-K2: partials of z @ W_z   (lda=LATENT, kLen=128)
    dim3 g1(HID / 64, (Bsz + 63) / 64, 2);
    gemm_part<<<g1, 128>>>(z, LATENT, W_z, gpart, Bsz, HID, LATENT / 2);

    // h = relu(part0 + part1 + b_z)
    combine1_kernel<<<(Bsz * HID / 4) / 256, 256>>>(
        gpart, gpart + (size_t)MAXB * HID, b_z, gh);

    // gemm2 split-K4: partials of h @ W_e1_sum   (lda=HID, kLen=128)
    dim3 g2(HID / 64, (Bsz + 63) / 64, 4);
    gemm_part<<<g2, 128>>>(gh, HID, gws, gpart, Bsz, HID, HID / 4);

    // gp[b] = dot(relu(Σ parts + b_e1), W_e2)
    combine2_kernel<<<(Bsz + 7) / 8, 256>>>(gpart, b_e1, W_e2, gpp, Bsz);

    // logits + p + broadcast writes
    dim3 fgrid(Bsz, 2);
    finalize_kernel<<<fgrid, 256>>>(gh, gpp, W_node, b_node, b_e2,
                                    out, Bsz, N, has_edges);
}

// round 14
// speedup vs baseline: 1.1649x; 1.1649x over previous
#include <cuda_runtime.h>
#include <math.h>

#define LATENT 256
#define HID 512
#define NT 16
#define MAXB 2048

// scratch (allocation-free rule: device globals)
__device__ float g_h[MAXB * HID];
__device__ float g_we1s[HID * HID];
__device__ float g_p[MAXB];
__device__ float g_part[4][MAXB * HID];   // split-K partial sums

// ---------------------------------------------------------------------------
// W_e1_sum = W_e1[0:H, :] + W_e1[H:2H, :]
// ---------------------------------------------------------------------------
__global__ __launch_bounds__(256)
void wsum_kernel(const float* __restrict__ W, float* __restrict__ o)
{
    int i = blockIdx.x * 256 + threadIdx.x;   // over HID*HID/4 float4s
    float4 a = reinterpret_cast<const float4*>(W)[i];
    float4 b = reinterpret_cast<const float4*>(W + (size_t)HID * HID)[i];
    a.x += b.x; a.y += b.y; a.z += b.z; a.w += b.w;
    reinterpret_cast<float4*>(o)[i] = a;
}

// ---------------------------------------------------------------------------
// Split-K SGEMM partial (R12-proven scalar mainloop):
//   Cpart[z] = A[:, kOff:kOff+kLen] @ B[kOff:kOff+kLen, :]  (raw store)
// BM=64 BN=64 BK=16, 128 threads, 8x4 microtile, double-buffered.
// grid = (N/64, ceil(M/64), nsplit); kOff = blockIdx.z * kLen.
// ---------------------------------------------------------------------------
__global__ __launch_bounds__(128)
void gemm_part(const float* __restrict__ A, int lda,
               const float* __restrict__ B,
               float* __restrict__ Cpart,
               int M, int N, int kLen)
{
    constexpr int BM = 64, BN = 64, BK = 16, AP = BM + 4;
    __shared__ __align__(16) float As[2][BK][AP];
    __shared__ __align__(16) float Bs[2][BK][BN];

    const int tx = threadIdx.x;
    const int rowBase = blockIdx.y * BM;
    const int colBase = blockIdx.x * BN;
    const int kOff = blockIdx.z * kLen;
    float* C = Cpart + (size_t)blockIdx.z * MAXB * HID;

    const int ar = tx >> 2;            // rows ar, ar+32
    const int ac = (tx & 3) << 2;
    const int br = tx >> 4;            // rows br, br+8
    const int bc = (tx & 15) << 2;

    const int rm0 = (tx >> 4) << 3;
    const int cn0 = (tx & 15) << 2;

    const bool mok0 = (rowBase + ar) < M;
    const bool mok1 = (rowBase + ar + 32) < M;
    const float* Ap0 = A + (size_t)(rowBase + ar) * lda + kOff + ac;
    const float* Ap1 = Ap0 + (size_t)32 * lda;
    const float* Bp  = B + (size_t)(kOff + br) * N + colBase + bc;

    float acc[8][4] = {};

    // stage 0
    float4 av0 = make_float4(0.f,0.f,0.f,0.f), av1 = av0;
    if (mok0) av0 = *reinterpret_cast<const float4*>(Ap0);
    if (mok1) av1 = *reinterpret_cast<const float4*>(Ap1);
    float4 bv0 = *reinterpret_cast<const float4*>(Bp);
    float4 bv1 = *reinterpret_cast<const float4*>(Bp + (size_t)8 * N);
    {
        const float* a0p = &av0.x; const float* a1p = &av1.x;
        #pragma unroll
        for (int i = 0; i < 4; i++) {
            As[0][ac + i][ar]      = a0p[i];
            As[0][ac + i][ar + 32] = a1p[i];
        }
        *reinterpret_cast<float4*>(&Bs[0][br][bc])     = bv0;
        *reinterpret_cast<float4*>(&Bs[0][br + 8][bc]) = bv1;
    }
    __syncthreads();

    const int nk = kLen / BK;
    for (int t = 0; t < nk; t++) {
        const int buf = t & 1;

        if (t + 1 < nk) {
            av0 = make_float4(0.f,0.f,0.f,0.f); av1 = av0;
            if (mok0) av0 = *reinterpret_cast<const float4*>(Ap0 + (t + 1) * BK);
            if (mok1) av1 = *reinterpret_cast<const float4*>(Ap1 + (t + 1) * BK);
            bv0 = *reinterpret_cast<const float4*>(Bp + (size_t)((t + 1) * BK) * N);
            bv1 = *reinterpret_cast<const float4*>(Bp + (size_t)((t + 1) * BK + 8) * N);
        }

        #pragma unroll
        for (int kk = 0; kk < BK; kk++) {
            float4 a0 = *reinterpret_cast<const float4*>(&As[buf][kk][rm0]);
            float4 a1 = *reinterpret_cast<const float4*>(&As[buf][kk][rm0 + 4]);
            float4 b  = *reinterpret_cast<const float4*>(&Bs[buf][kk][cn0]);
            float arr[8] = {a0.x,a0.y,a0.z,a0.w,a1.x,a1.y,a1.z,a1.w};
            float brr[4] = {b.x,b.y,b.z,b.w};
            #pragma unroll
            for (int i = 0; i < 8; i++)
                #pragma unroll
                for (int j = 0; j < 4; j++)
                    acc[i][j] = fmaf(arr[i], brr[j], acc[i][j]);
        }

        if (t + 1 < nk) {
            const int nb = buf ^ 1;
            const float* a0p = &av0.x; const float* a1p = &av1.x;
            #pragma unroll
            for (int i = 0; i < 4; i++) {
                As[nb][ac + i][ar]      = a0p[i];
                As[nb][ac + i][ar + 32] = a1p[i];
            }
            *reinterpret_cast<float4*>(&Bs[nb][br][bc])     = bv0;
            *reinterpret_cast<float4*>(&Bs[nb][br + 8][bc]) = bv1;
        }
        __syncthreads();
    }

    #pragma unroll
    for (int i = 0; i < 8; i++) {
        int r = rowBase + rm0 + i;
        if (r < M)
            *reinterpret_cast<float4*>(C + (size_t)r * N + colBase + cn0) =
                make_float4(acc[i][0], acc[i][1], acc[i][2], acc[i][3]);
    }
}

// ---------------------------------------------------------------------------
// combine1: h = relu(part0 + part1 + b_z)   (elementwise, float4)
// ---------------------------------------------------------------------------
__global__ __launch_bounds__(256)
void combine1_kernel(const float* __restrict__ p0,
                     const float* __restrict__ p1,
                     const float* __restrict__ bz,
                     float* __restrict__ h)
{
    int i = blockIdx.x * 256 + threadIdx.x;   // float4 index over Bsz*HID/4
    float4 a = reinterpret_cast<const float4*>(p0)[i];
    float4 b = reinterpret_cast<const float4*>(p1)[i];
    float4 c = reinterpret_cast<const float4*>(bz)[i & 127];
    float4 v;
    v.x = fmaxf(a.x + b.x + c.x, 0.f);
    v.y = fmaxf(a.y + b.y + c.y, 0.f);
    v.z = fmaxf(a.z + b.z + c.z, 0.f);
    v.w = fmaxf(a.w + b.w + c.w, 0.f);
    reinterpret_cast<float4*>(h)[i] = v;
}

// ---------------------------------------------------------------------------
// combine2: gp[b] = dot(relu(Σ parts[0..3] + b_e1), W_e2) — warp-per-row
// ---------------------------------------------------------------------------
__global__ __launch_bounds__(256)
void combine2_kernel(const float* __restrict__ parts,
                     const float* __restrict__ be1,
                     const float* __restrict__ we2,
                     float* __restrict__ gp, int Bsz)
{
    const int warp = threadIdx.x >> 5, lane = threadIdx.x & 31;
    const int r = blockIdx.x * 8 + warp;
    if (r >= Bsz) return;

    const float4* P0 = reinterpret_cast<const float4*>(parts + (size_t)r * HID);
    const float4* P1 = reinterpret_cast<const float4*>(parts + (size_t)MAXB * HID + (size_t)r * HID);
    const float4* P2 = reinterpret_cast<const float4*>(parts + (size_t)2 * MAXB * HID + (size_t)r * HID);
    const float4* P3 = reinterpret_cast<const float4*>(parts + (size_t)3 * MAXB * HID + (size_t)r * HID);
    const float4* B4 = reinterpret_cast<const float4*>(be1);
    const float4* W4 = reinterpret_cast<const float4*>(we2);

    float s = 0.f;
    #pragma unroll
    for (int q = 0; q < 4; q++) {
        int f = q * 32 + lane;        // 128 float4 per row
        float4 a = P0[f], b = P1[f], c = P2[f], d = P3[f];
        float4 bb = B4[f], w = W4[f];
        float x0 = fmaxf(a.x + b.x + c.x + d.x + bb.x, 0.f);
        float x1 = fmaxf(a.y + b.y + c.y + d.y + bb.y, 0.f);
        float x2 = fmaxf(a.z + b.z + c.z + d.z + bb.z, 0.f);
        float x3 = fmaxf(a.w + b.w + c.w + d.w + bb.w, 0.f);
        s = fmaf(x0, w.x, s);
        s = fmaf(x1, w.y, s);
        s = fmaf(x2, w.z, s);
        s = fmaf(x3, w.w, s);
    }
    #pragma unroll
    for (int off = 16; off; off >>= 1)
        s += __shfl_down_sync(0xffffffffu, s, off);
    if (lane == 0) gp[r] = s;
}

// ---------------------------------------------------------------------------
// finalize: grid (Bsz, 5) — balanced small blocks.
//   y==0:    logits[t] = h[b].W_node[:,t] + b_node[t]; broadcast over N rows.
//   y==1..4: p = sigmoid(g_p[b] + b_e2); strict-lower-tri rows
//            [ (y-1)*N/4, y*N/4 ).
// ---------------------------------------------------------------------------
__global__ __launch_bounds__(256)
void finalize_kernel(const float* __restrict__ g_h_p,
                     const float* __restrict__ gp,
                     const float* __restrict__ W_node,
                     const float* __restrict__ b_node,
                     const float* __restrict__ b_e2,
                     float* __restrict__ out,
                     int Bsz, int N, int has_edges)
{
    const int b = blockIdx.x;
    const int tid = threadIdx.x;
    const int warp = tid >> 5, lane = tid & 31;

    if (blockIdx.y == 0) {
        // ---------------- logits path ----------------
        __shared__ float sh_h[HID];
        __shared__ float sh_logits[NT];
        __shared__ float sacc[8][4][4];

        {
            const float2* hp = reinterpret_cast<const float2*>(g_h_p + (size_t)b * HID);
            reinterpret_cast<float2*>(sh_h)[tid] = hp[tid];
        }
        __syncthreads();

        const float4* W4 = reinterpret_cast<const float4*>(W_node);
        float a0 = 0.f, a1 = 0.f, a2 = 0.f, a3 = 0.f;
        #pragma unroll
        for (int i = 0; i < (HID * NT / 4) / 256; i++) {
            int j = tid + i * 256;
            float hv = sh_h[j >> 2];
            float4 w = W4[j];
            a0 = fmaf(hv, w.x, a0);
            a1 = fmaf(hv, w.y, a1);
            a2 = fmaf(hv, w.z, a2);
            a3 = fmaf(hv, w.w, a3);
        }
        #pragma unroll
        for (int off = 16; off >= 4; off >>= 1) {
            a0 += __shfl_down_sync(0xffffffffu, a0, off);
            a1 += __shfl_down_sync(0xffffffffu, a1, off);
            a2 += __shfl_down_sync(0xffffffffu, a2, off);
            a3 += __shfl_down_sync(0xffffffffu, a3, off);
        }
        if (lane < 4) {
            sacc[warp][lane][0] = a0;
            sacc[warp][lane][1] = a1;
            sacc[warp][lane][2] = a2;
            sacc[warp][lane][3] = a3;
        }
        __syncthreads();
        if (tid < NT) {
            float s = 0.f;
            #pragma unroll
            for (int w = 0; w < 8; w++)
                s += sacc[w][tid >> 2][tid & 3];
            sh_logits[tid] = s + b_node[tid];
        }
        __syncthreads();

        size_t base1 = (size_t)b * N * NT;
        if (((N * NT) & 3) == 0) {
            float4 myv = *reinterpret_cast<const float4*>(&sh_logits[(tid & 3) << 2]);
            float4* o4 = reinterpret_cast<float4*>(out + base1);
            int n4 = (N * NT) >> 2;
            for (int i = tid; i < n4; i += 256)
                o4[i] = myv;
        } else {
            for (int i = tid; i < N * NT; i += 256)
                out[base1 + i] = sh_logits[i & (NT - 1)];
        }
        return;
    }

    // ---------------- edges path (slice s = blockIdx.y - 1) ----------------
    if (!has_edges) return;
    const int s = blockIdx.y - 1;
    const float p = 1.f / (1.f + expf(-(gp[b] + b_e2[0])));
    size_t base2 = (size_t)Bsz * N * NT + (size_t)b * N * N;

    if (N == 128) {
        // slice covers rows s*32 .. s*32+31; warp handles 4 rows, lane = 1 f4
        const int j0 = lane << 2;
        const int i0 = s * 32 + warp;
        float4* rowp = reinterpret_cast<float4*>(out + base2)
                       + (size_t)i0 * 32 + lane;
        #pragma unroll
        for (int r = 0; r < 4; r++) {
            const int i = i0 + (r << 3);
            const int d = i - j0;
            float4 v;
            v.x = (d > 0) ? p : 0.f;
            v.y = (d > 1) ? p : 0.f;
            v.z = (d > 2) ? p : 0.f;
            v.w = (d > 3) ? p : 0.f;
            *rowp = v;
            rowp += 8 * 32;
        }
    } else if ((N & 3) == 0) {
        float4* e4 = reinterpret_cast<float4*>(out + base2);
        const int nr4 = N >> 2;
        const int i0 = (s * N) >> 2, i1 = ((s + 1) * N) >> 2;
        for (int i = i0 + warp; i < i1; i += 8) {
            float4* row = e4 + (size_t)i * nr4;
            for (int c = lane; c < nr4; c += 32) {
                int j0 = c << 2;
                float4 v;
                v.x = (j0 + 0 < i) ? p : 0.f;
                v.y = (j0 + 1 < i) ? p : 0.f;
                v.z = (j0 + 2 < i) ? p : 0.f;
                v.w = (j0 + 3 < i) ? p : 0.f;
                row[c] = v;
            }
        }
    } else {
        const int i0 = (s * N) >> 2, i1 = ((s + 1) * N) >> 2;
        for (int i = i0 + warp; i < i1; i += 8) {
            float* row = out + base2 + (size_t)i * N;
            for (int j = lane; j < N; j += 32)
                row[j] = (j < i) ? p : 0.f;
        }
    }
}

// ---------------------------------------------------------------------------
// Inputs (metadata order): z, num_nodes, W_z, b_z, W_node, b_node,
//                          W_e1, b_e1, W_e2, b_e2
// num_nodes sits in device memory; derive N on host from out_size.
// ---------------------------------------------------------------------------
extern "C" void kernel_launch(void* const* d_in, const int* in_sizes, int n_in,
                              void* d_out, int out_size)
{
    const float* z      = (const float*)d_in[0];
    const float* W_z    = (const float*)d_in[2];
    const float* b_z    = (const float*)d_in[3];
    const float* W_node = (const float*)d_in[4];
    const float* b_node = (const float*)d_in[5];
    const float* W_e1   = (const float*)d_in[6];
    const float* b_e1   = (const float*)d_in[7];
    const float* W_e2   = (const float*)d_in[8];
    const float* b_e2   = (const float*)d_in[9];
    float* out = (float*)d_out;

    int Bsz = in_sizes[0] / LATENT;
    long per = (long)out_size / (long)Bsz;

    double disc = (double)NT * NT + 4.0 * (double)per;
    int N = (int)((-(double)NT + sqrt(disc)) * 0.5 + 0.5);
    int has_edges = 1;
    if ((long)N * N + (long)NT * N != per) {
        N = (int)(per / NT);
        has_edges = 0;
    }

    float *gh = nullptr, *gws = nullptr, *gpp = nullptr, *gpart = nullptr;
    cudaGetSymbolAddress((void**)&gh,    g_h);
    cudaGetSymbolAddress((void**)&gws,   g_we1s);
    cudaGetSymbolAddress((void**)&gpp,   g_p);
    cudaGetSymbolAddress((void**)&gpart, g_part);

    // W_e1 half-sum
    wsum_kernel<<<(HID * HID / 4) / 256, 256>>>(W_e1, gws);

    // gemm1 split-K2: partials of z @ W_z   (lda=LATENT, kLen=128)
    dim3 g1(HID / 64, (Bsz + 63) / 64, 2);
    gemm_part<<<g1, 128>>>(z, LATENT, W_z, gpart, Bsz, HID, LATENT / 2);

    // h = relu(part0 + part1 + b_z)
    combine1_kernel<<<(Bsz * HID / 4) / 256, 256>>>(
        gpart, gpart + (size_t)MAXB * HID, b_z, gh);

    // gemm2 split-K4: partials of h @ W_e1_sum   (lda=HID, kLen=128)
    dim3 g2(HID / 64, (Bsz + 63) / 64, 4);
    gemm_part<<<g2, 128>>>(gh, HID, gws, gpart, Bsz, HID, HID / 4);

    // gp[b] = dot(relu(Σ parts + b_e1), W_e2)
    combine2_kernel<<<(Bsz + 7) / 8, 256>>>(gpart, b_e1, W_e2, gpp, Bsz);

    // logits + p + broadcast writes (balanced small blocks)
    dim3 fgrid(Bsz, 5);
    finalize_kernel<<<fgrid, 256>>>(gh, gpp, W_node, b_node, b_e2,
                                    out, Bsz, N, has_edges);
}